// round 12
// baseline (speedup 1.0000x reference)
#include <cuda_runtime.h>
#include <cuda_bf16.h>
#include <math.h>
#include <stdint.h>

#define BB 16
#define CC 32
#define NN 512
#define T1 192
#define T2 96
#define L1 97
#define L2 49
#define EE 64

typedef unsigned long long ull;
typedef __nv_bfloat16 bf16;

static constexpr size_t SZ1 = (size_t)BB*CC*NN*T1;
static constexpr size_t SZ2 = (size_t)BB*CC*NN*T2;

// ---------------- scratch ----------------
__device__ float g_bufA[SZ1];
__device__ float g_bufB[SZ1];
__device__ float g_bufC[SZ1];
__device__ float g_bufD[SZ2];
__device__ float g_bufF[SZ2];
__device__ float g_Mc[CC*T1*T1];
__device__ float g_Mt[CC*T1*T1];
__device__ float g_D1[CC*T1*T2];
__device__ float g_C2[CC*T2*T2];
__device__ float g_cos1[L1*T1];
__device__ float g_sin1[L1*T1];
__device__ float g_cos2[L2*T2];
__device__ float g_sin2[L2*T2];
__device__ float g_K1[CC*T1];
__device__ float g_K2[CC*T2];
__device__ float g_featP[BB*CC*4*T1];
__device__ float g_gate[BB*T1];
// pre-split bf16 weights
__device__ bf16 g_Bin[2*2*4*96*T1];
__device__ bf16 g_Bout[2*1*4*96*T2];
__device__ bf16 g_McB[CC*2*192*384];
__device__ bf16 g_D1B[CC*2*96*T1];
__device__ bf16 g_C2B[CC*2*96*T2];

// ---------------- f32x2 helpers ----------------
__device__ __forceinline__ ull pk2(float lo, float hi) {
    ull r; asm("mov.b64 %0, {%1,%2};" : "=l"(r) : "f"(lo), "f"(hi)); return r;
}
__device__ __forceinline__ void fma2(ull& d, ull a, ull b) {
    asm("fma.rn.f32x2 %0, %1, %2, %0;" : "+l"(d) : "l"(a), "l"(b));
}
__device__ __forceinline__ float2 upk2(ull v) {
    float2 f; asm("mov.b64 {%0,%1}, %2;" : "=f"(f.x), "=f"(f.y) : "l"(v)); return f;
}

__device__ __forceinline__ float gelu_t(float x) {
    float x3 = x*x*x;
    return 0.5f*x*(1.0f + tanhf(0.7978845608028654f*(x + 0.044715f*x3)));
}

__device__ __forceinline__ uint32_t smem_u32(const void* p) {
    uint32_t a;
    asm("{ .reg .u64 t; cvta.to.shared.u64 t, %1; cvt.u32.u64 %0, t; }" : "=r"(a) : "l"(p));
    return a;
}

// ---------------- mma.sync helpers ----------------
#define LDM4(r, addr) \
    asm volatile("ldmatrix.sync.aligned.m8n8.x4.shared.b16 {%0,%1,%2,%3}, [%4];" \
        : "=r"((r)[0]), "=r"((r)[1]), "=r"((r)[2]), "=r"((r)[3]) : "r"(addr))

#define MMA_BF16(c, a, b0, b1) \
    asm volatile("mma.sync.aligned.m16n8k16.row.col.f32.bf16.bf16.f32 " \
        "{%0,%1,%2,%3},{%4,%5,%6,%7},{%8,%9},{%0,%1,%2,%3};" \
        : "+f"((c)[0]), "+f"((c)[1]), "+f"((c)[2]), "+f"((c)[3]) \
        : "r"((a)[0]), "r"((a)[1]), "r"((a)[2]), "r"((a)[3]), "r"(b0), "r"(b1))

__device__ __forceinline__ void cvt_hilo_store(float4 v0, float4 v1, bf16* dH, bf16* dL) {
    __nv_bfloat162 h0 = __floats2bfloat162_rn(v0.x, v0.y);
    __nv_bfloat162 h1 = __floats2bfloat162_rn(v0.z, v0.w);
    __nv_bfloat162 h2 = __floats2bfloat162_rn(v1.x, v1.y);
    __nv_bfloat162 h3 = __floats2bfloat162_rn(v1.z, v1.w);
    __nv_bfloat162 l0 = __floats2bfloat162_rn(v0.x - __bfloat162float(h0.x), v0.y - __bfloat162float(h0.y));
    __nv_bfloat162 l1 = __floats2bfloat162_rn(v0.z - __bfloat162float(h1.x), v0.w - __bfloat162float(h1.y));
    __nv_bfloat162 l2 = __floats2bfloat162_rn(v1.x - __bfloat162float(h2.x), v1.y - __bfloat162float(h2.y));
    __nv_bfloat162 l3 = __floats2bfloat162_rn(v1.z - __bfloat162float(h3.x), v1.w - __bfloat162float(h3.y));
    *(uint4*)dH = make_uint4(*(uint32_t*)&h0, *(uint32_t*)&h1, *(uint32_t*)&h2, *(uint32_t*)&h3);
    *(uint4*)dL = make_uint4(*(uint32_t*)&l0, *(uint32_t*)&l1, *(uint32_t*)&l2, *(uint32_t*)&l3);
}

// ---------------- precompute ----------------
__global__ void k_tables() {
    int i = blockIdx.x*blockDim.x + threadIdx.x;
    if (i < L1*T1) {
        int h = i / T1, t = i % T1;
        int m = (h*t) % T1;
        float a = (float)m * (1.0f/96.0f);
        g_cos1[i] = cospif(a);
        g_sin1[i] = sinpif(a);
    }
    int j = i - L1*T1;
    if (j >= 0 && j < L2*T2) {
        int h = j / T2, t = j % T2;
        int m = (h*t) % T2;
        float a = (float)m * (1.0f/48.0f);
        g_cos2[j] = cospif(a);
        g_sin2[j] = sinpif(a);
    }
}

__global__ void k_buildM(const float* __restrict__ Lc, const float* __restrict__ Lt) {
    int t = blockIdx.x, l = blockIdx.y, tp = threadIdx.x;
    float ac = 0.f, as = 0.f;
    for (int h = 0; h < L1; h++) {
        float w = (h == 0 || h == L1-1) ? (1.0f/T1) : (2.0f/T1);
        float lc = Lc[l*L1+h]*w, lt = Lt[l*L1+h]*w;
        ac = fmaf(lc * g_cos1[h*T1+t], g_cos1[h*T1+tp], ac);
        as = fmaf(lt * g_sin1[h*T1+t], g_sin1[h*T1+tp], as);
    }
    size_t o = ((size_t)l*T1 + t)*T1 + tp;
    g_Mc[o] = ac;
    g_Mt[o] = as;
}

__global__ void k_buildK1(const float* __restrict__ Wr, const float* __restrict__ Wi) {
    int i = blockIdx.x*blockDim.x + threadIdx.x;
    if (i >= CC*T1) return;
    int c = i / T1, d = i % T1;
    float acc = 0.f;
    for (int h = 0; h < L1; h++) {
        float w = (h == 0 || h == L1-1) ? (1.0f/T1) : (2.0f/T1);
        acc += w * (Wr[c*L1+h]*g_cos1[h*T1+d] - Wi[c*L1+h]*g_sin1[h*T1+d]);
    }
    g_K1[i] = acc;
}

__global__ void k_buildD1(const float* __restrict__ Wfc) {
    __shared__ float kr[2*T1];
    int t = blockIdx.x, c = blockIdx.y, s2 = threadIdx.x;
    for (int s = s2; s < T1; s += T2) {
        float v = g_K1[c*T1 + s];
        kr[s] = v; kr[s + T1] = v;
    }
    __syncthreads();
    float acc = 0.f;
    const float* kb = kr + (T1 - t);
    for (int s = 0; s < T1; s++)
        acc = fmaf(kb[s], Wfc[s*T2 + s2], acc);
    g_D1[((size_t)c*T1 + t)*T2 + s2] = acc;
}

__global__ void k_buildK2(const float* __restrict__ Wr, const float* __restrict__ Wi) {
    int i = blockIdx.x*blockDim.x + threadIdx.x;
    if (i >= CC*T2) return;
    int c = i / T2, d = i % T2;
    float acc = 0.f;
    for (int h = 0; h < L2; h++) {
        float w = (h == 0 || h == L2-1) ? (1.0f/T2) : (2.0f/T2);
        acc += w * (Wr[c*L2+h]*g_cos2[h*T2+d] - Wi[c*L2+h]*g_sin2[h*T2+d]);
    }
    g_K2[i] = acc;
}
__global__ void k_expand2() {
    size_t i = (size_t)blockIdx.x*blockDim.x + threadIdx.x;
    if (i >= (size_t)CC*T2*T2) return;
    int s = (int)(i % T2);
    int t = (int)((i / T2) % T2);
    int c = (int)(i / ((size_t)T2*T2));
    g_C2[i] = g_K2[c*T2 + ((s - t + T2) % T2)];
}

template<int KTOT, int HALVES>
__global__ void k_splitW(const float* __restrict__ W1, const float* __restrict__ W2,
                         bf16* __restrict__ dst) {
    int total = 2*HALVES*4*96*KTOT;
    int idx = blockIdx.x*blockDim.x + threadIdx.x;
    if (idx >= total) return;
    int k     = idx % KTOT;
    int n     = (idx / KTOT) % 96;
    int mat   = (idx / (KTOT*96)) % 4;
    int half  = (idx / (KTOT*96*4)) % HALVES;
    int layer = idx / (KTOT*96*4*HALVES);
    const float* src = (mat < 2) ? W1 : W2;
    int s = half*96 + n;
    float w = src[(size_t)layer*KTOT*KTOT + (size_t)k*KTOT + s];
    bf16 hi = __float2bfloat16(w);
    bf16 v = (mat & 1) ? __float2bfloat16(w - __bfloat162float(hi)) : hi;
    dst[idx] = v;
}

__global__ void k_splitMM() {
    size_t total = (size_t)CC*2*192*384;
    size_t idx = (size_t)blockIdx.x*blockDim.x + threadIdx.x;
    if (idx >= total) return;
    int k     = (int)(idx % 384);
    int n     = (int)((idx / 384) % 192);
    int plane = (int)((idx / (384*192)) % 2);
    int c     = (int)(idx / (384*192*2));
    float w = (k < 192) ? g_Mc[((size_t)c*T1 + k)*T1 + n]
                        : g_Mt[((size_t)c*T1 + (k-192))*T1 + n];
    bf16 hi = __float2bfloat16(w);
    g_McB[idx] = plane ? __float2bfloat16(w - __bfloat162float(hi)) : hi;
}

__global__ void k_splitD1() {
    int total = CC*2*96*T1;
    int idx = blockIdx.x*blockDim.x + threadIdx.x;
    if (idx >= total) return;
    int k     = idx % T1;
    int n     = (idx / T1) % 96;
    int plane = (idx / (T1*96)) % 2;
    int c     = idx / (T1*96*2);
    float w = g_D1[((size_t)c*T1 + k)*T2 + n];
    bf16 hi = __float2bfloat16(w);
    g_D1B[idx] = plane ? __float2bfloat16(w - __bfloat162float(hi)) : hi;
}

__global__ void k_splitC2() {
    int total = CC*2*96*T2;
    int idx = blockIdx.x*blockDim.x + threadIdx.x;
    if (idx >= total) return;
    int k     = idx % T2;
    int n     = (idx / T2) % 96;
    int plane = (idx / (T2*96)) % 2;
    int c     = idx / (T2*96*2);
    float w = g_C2[((size_t)c*T2 + k)*T2 + n];
    bf16 hi = __float2bfloat16(w);
    g_C2B[idx] = plane ? __float2bfloat16(w - __bfloat162float(hi)) : hi;
}

// ---------------- channel mix ----------------
__global__ void __launch_bounds__(256) k_chmix(const float* __restrict__ x,
                                               const float* __restrict__ Gc,
                                               const float* __restrict__ Gt) {
    __shared__ __align__(16) float2 sG[CC*CC];
    int tid = threadIdx.x;
    for (int i = tid; i < CC*CC; i += 256) sG[i] = make_float2(Gc[i], Gt[i]);
    __syncthreads();
    int b = blockIdx.y;
    size_t m = (size_t)blockIdx.x*256 + tid;
    ull a[CC];
#pragma unroll
    for (int l = 0; l < CC; l++) a[l] = 0ull;
    for (int c = 0; c < CC; c++) {
        float xv = x[((size_t)(b*CC + c)*NN)*T1 + m];
        ull xp = pk2(xv, xv);
#pragma unroll
        for (int l = 0; l < CC; l++) fma2(a[l], xp, *(const ull*)&sG[c*CC + l]);
    }
#pragma unroll
    for (int l = 0; l < CC; l++) {
        float2 p = upk2(a[l]);
        g_bufA[((size_t)(b*CC + l)*NN)*T1 + m] = p.x;
        g_bufB[((size_t)(b*CC + l)*NN)*T1 + m] = p.y;
    }
}

// ---------------- mm2 (tensor, merged N=192): Y = resid + [u|v] @ [Mc;Mt][c] ----------------
__global__ void __launch_bounds__(256) k_mm2MMA(const float* __restrict__ U,
                                                const float* __restrict__ V,
                                                const float* __restrict__ resid,
                                                float* __restrict__ Y) {
    constexpr int AST = 40;
    __shared__ __align__(16) bf16 sAh[64*AST];
    __shared__ __align__(16) bf16 sAl[64*AST];
    __shared__ __align__(16) bf16 sB[2*192*AST];
    int tid = threadIdx.x, lane = tid & 31, wid = tid >> 5;
    int wm = wid & 3, wn = wid >> 2;
    int c = blockIdx.y, b = blockIdx.z;
    size_t row0 = (size_t)(b*CC + c)*NN + (size_t)blockIdx.x*64;
    const bf16* Wc = g_McB + (size_t)c*2*192*384;

    float cc[12][4];
#pragma unroll
    for (int i = 0; i < 12; i++)
#pragma unroll
        for (int j = 0; j < 4; j++) cc[i][j] = 0.f;

    uint32_t aOff = (uint32_t)((wm*16 + (lane & 15))*AST + ((lane >> 4) << 3)) * 2;
    uint32_t aAddrH = smem_u32(sAh) + aOff;
    uint32_t aAddrL = smem_u32(sAl) + aOff;
    uint32_t bRow = (uint32_t)((lane & 7) + ((lane >> 4) << 3));
    uint32_t bOff = (bRow*AST + (((lane >> 3) & 1) << 3)) * 2;
    uint32_t sBbase = smem_u32(sB);

    int arow = tid >> 2, akg = (tid & 3) * 8;
    bf16* aDstH = &sAh[arow*AST + akg];
    bf16* aDstL = &sAl[arow*AST + akg];

    float4 nx0, nx1;
    uint4 nB[6];
    {
        const float* xr = U + (row0 + arow)*T1 + akg;
        nx0 = *(const float4*)xr; nx1 = *(const float4*)(xr + 4);
#pragma unroll
        for (int it = 0; it < 6; it++) {
            int i = tid + it*256;
            int plane = i / 768, rem = i % 768;
            int n = rem >> 2, kg = (rem & 3) * 8;
            nB[it] = *(const uint4*)&Wc[((size_t)plane*192 + n)*384 + kg];
        }
    }
    for (int kc = 0; kc < 12; kc++) {
        cvt_hilo_store(nx0, nx1, aDstH, aDstL);
#pragma unroll
        for (int it = 0; it < 6; it++) {
            int i = tid + it*256;
            int plane = i / 768, rem = i % 768;
            int n = rem >> 2, kg = (rem & 3) * 8;
            *(uint4*)&sB[(plane*192 + n)*AST + kg] = nB[it];
        }
        __syncthreads();
        if (kc + 1 < 12) {
            int kn = kc + 1;
            const float* Xs = (kn < 6) ? U : V;
            int kl = (kn < 6) ? kn : kn - 6;
            const float* xr = Xs + (row0 + arow)*T1 + kl*32 + akg;
            nx0 = *(const float4*)xr; nx1 = *(const float4*)(xr + 4);
#pragma unroll
            for (int it = 0; it < 6; it++) {
                int i = tid + it*256;
                int plane = i / 768, rem = i % 768;
                int n = rem >> 2, kg = (rem & 3) * 8;
                nB[it] = *(const uint4*)&Wc[((size_t)plane*192 + n)*384 + kn*32 + kg];
            }
        }
#pragma unroll
        for (int k16 = 0; k16 < 2; k16++) {
            uint32_t kof = (uint32_t)(k16 * 32);
            uint32_t ah[4], al[4];
            LDM4(ah, aAddrH + kof);
            LDM4(al, aAddrL + kof);
            uint32_t baseH = sBbase + bOff + kof;
            uint32_t baseL = baseH + (uint32_t)(192*AST)*2;
#pragma unroll
            for (int pr = 0; pr < 6; pr++) {
                uint32_t po = (uint32_t)((wn*96 + pr*16)*AST)*2;
                uint32_t bh[4], bl[4];
                LDM4(bh, baseH + po);
                LDM4(bl, baseL + po);
                MMA_BF16(cc[2*pr],   ah, bh[0], bh[1]);
                MMA_BF16(cc[2*pr+1], ah, bh[2], bh[3]);
                MMA_BF16(cc[2*pr],   al, bh[0], bh[1]);
                MMA_BF16(cc[2*pr+1], al, bh[2], bh[3]);
                MMA_BF16(cc[2*pr],   ah, bl[0], bl[1]);
                MMA_BF16(cc[2*pr+1], ah, bl[2], bl[3]);
            }
        }
        __syncthreads();
    }

    int g = lane >> 2, tg = lane & 3;
    size_t mrow = row0 + (size_t)wm*16 + g;
    int colb = wn*96 + tg*2;
#pragma unroll
    for (int nf = 0; nf < 12; nf++) {
        int col = colb + nf*8;
        float2 r0 = *(const float2*)&resid[mrow*T1 + col];
        float2 r1 = *(const float2*)&resid[(mrow + 8)*T1 + col];
        *(float2*)&Y[mrow*T1 + col]       = make_float2(cc[nf][0] + r0.x, cc[nf][1] + r0.y);
        *(float2*)&Y[(mrow + 8)*T1 + col] = make_float2(cc[nf][2] + r1.x, cc[nf][3] + r1.y);
    }
}

// ---------------- channel GEMM (tensor): Y = (X1 + sg*X2) @ W[c] [+bias] ----------------
template<int KTOT, bool BIAS>
__global__ void __launch_bounds__(256) k_cgemmMMA(const float* __restrict__ X1,
                                                  const float* __restrict__ X2,
                                                  const bf16* __restrict__ WB,
                                                  const float* __restrict__ bias,
                                                  const float* __restrict__ gate,
                                                  float* __restrict__ Y) {
    constexpr int AST = 40, KC = KTOT/32;
    __shared__ __align__(16) bf16 sAh[64*AST];
    __shared__ __align__(16) bf16 sAl[64*AST];
    __shared__ __align__(16) bf16 sB[2*96*AST];
    __shared__ float sg[KTOT];
    int tid = threadIdx.x, lane = tid & 31, wid = tid >> 5;
    int wm = wid & 3, wn = wid >> 2;
    int c = blockIdx.y, b = blockIdx.z;
    size_t row0 = (size_t)(b*CC + c)*NN + (size_t)blockIdx.x*64;
    const bf16* Wc = WB + (size_t)c*2*96*KTOT;

    for (int t = tid; t < KTOT; t += 256) sg[t] = 1.0f + gate[b*KTOT + t];
    __syncthreads();

    float cc[6][4];
#pragma unroll
    for (int i = 0; i < 6; i++)
#pragma unroll
        for (int j = 0; j < 4; j++) cc[i][j] = 0.f;

    uint32_t aOff = (uint32_t)((wm*16 + (lane & 15))*AST + ((lane >> 4) << 3)) * 2;
    uint32_t aAddrH = smem_u32(sAh) + aOff;
    uint32_t aAddrL = smem_u32(sAl) + aOff;
    uint32_t bRow = (uint32_t)(wn*48 + (lane & 7) + ((lane >> 4) << 3));
    uint32_t bOff = (bRow*AST + (((lane >> 3) & 1) << 3)) * 2;
    uint32_t sBbase = smem_u32(sB);

    int arow = tid >> 2, akg = (tid & 3) * 8;
    const float* x1r = X1 + (row0 + arow)*KTOT;
    const float* x2r = X2 + (row0 + arow)*KTOT;
    bf16* aDstH = &sAh[arow*AST + akg];
    bf16* aDstL = &sAl[arow*AST + akg];

    float4 na0, na1, nb0, nb1;
    uint4 nB[3];
    {
        na0 = *(const float4*)&x1r[akg];
        na1 = *(const float4*)&x1r[akg + 4];
        nb0 = *(const float4*)&x2r[akg];
        nb1 = *(const float4*)&x2r[akg + 4];
#pragma unroll
        for (int it = 0; it < 3; it++) {
            int i = tid + it*256;
            int plane = i / 384, rem = i % 384;
            int n = rem >> 2, kg = (rem & 3) * 8;
            nB[it] = *(const uint4*)&Wc[((size_t)plane*96 + n)*KTOT + kg];
        }
    }
    for (int kc = 0; kc < KC; kc++) {
        {
            int k0 = kc*32 + akg;
            float4 v0 = na0, v1 = na1;
            v0.x = fmaf(nb0.x, sg[k0],   v0.x);
            v0.y = fmaf(nb0.y, sg[k0+1], v0.y);
            v0.z = fmaf(nb0.z, sg[k0+2], v0.z);
            v0.w = fmaf(nb0.w, sg[k0+3], v0.w);
            v1.x = fmaf(nb1.x, sg[k0+4], v1.x);
            v1.y = fmaf(nb1.y, sg[k0+5], v1.y);
            v1.z = fmaf(nb1.z, sg[k0+6], v1.z);
            v1.w = fmaf(nb1.w, sg[k0+7], v1.w);
            cvt_hilo_store(v0, v1, aDstH, aDstL);
#pragma unroll
            for (int it = 0; it < 3; it++) {
                int i = tid + it*256;
                int plane = i / 384, rem = i % 384;
                int n = rem >> 2, kg = (rem & 3) * 8;
                *(uint4*)&sB[(plane*96 + n)*AST + kg] = nB[it];
            }
        }
        __syncthreads();
        if (kc + 1 < KC) {
            int kn = (kc + 1)*32 + akg;
            na0 = *(const float4*)&x1r[kn];
            na1 = *(const float4*)&x1r[kn + 4];
            nb0 = *(const float4*)&x2r[kn];
            nb1 = *(const float4*)&x2r[kn + 4];
#pragma unroll
            for (int it = 0; it < 3; it++) {
                int i = tid + it*256;
                int plane = i / 384, rem = i % 384;
                int n = rem >> 2, kg = (rem & 3) * 8;
                nB[it] = *(const uint4*)&Wc[((size_t)plane*96 + n)*KTOT + (kc+1)*32 + kg];
            }
        }
#pragma unroll
        for (int k16 = 0; k16 < 2; k16++) {
            uint32_t kof = (uint32_t)(k16 * 32);
            uint32_t ah[4], al[4];
            LDM4(ah, aAddrH + kof);
            LDM4(al, aAddrL + kof);
            uint32_t baseH = sBbase + bOff + kof;
            uint32_t baseL = baseH + (uint32_t)(96*AST)*2;
#pragma unroll
            for (int pr = 0; pr < 3; pr++) {
                uint32_t po = (uint32_t)(pr*16*AST)*2;
                uint32_t bh[4], bl[4];
                LDM4(bh, baseH + po);
                LDM4(bl, baseL + po);
                MMA_BF16(cc[2*pr],   ah, bh[0], bh[1]);
                MMA_BF16(cc[2*pr+1], ah, bh[2], bh[3]);
                MMA_BF16(cc[2*pr],   al, bh[0], bh[1]);
                MMA_BF16(cc[2*pr+1], al, bh[2], bh[3]);
                MMA_BF16(cc[2*pr],   ah, bl[0], bl[1]);
                MMA_BF16(cc[2*pr+1], ah, bl[2], bl[3]);
            }
        }
        __syncthreads();
    }

    int g = lane >> 2, tg = lane & 3;
    size_t mrow = row0 + (size_t)wm*16 + g;
    int colb = wn*48 + tg*2;
#pragma unroll
    for (int nf = 0; nf < 6; nf++) {
        int col = colb + nf*8;
        float2 o0 = make_float2(cc[nf][0], cc[nf][1]);
        float2 o1 = make_float2(cc[nf][2], cc[nf][3]);
        if (BIAS) {
            float2 bv = *(const float2*)&bias[col];
            o0.x += bv.x; o0.y += bv.y; o1.x += bv.x; o1.y += bv.y;
        }
        *(float2*)&Y[mrow*96 + col]       = o0;
        *(float2*)&Y[(mrow + 8)*96 + col] = o1;
    }
}

// ---------------- tensor gmlp, M=128 tile + fused n-mean partials (dynamic smem) ----------------
// smem layout: sAh[128*40] @0 (10240B), sAl @10240, sB[4*96*40] @20480 (30720B),
//              sg @51200 (<=768B), sFP[8][48] @52096 (1536B)  => total 53632
template<int KTOT, bool G1>
__global__ void __launch_bounds__(256) k_gmlpMMA(const float* __restrict__ X,
                                                 const bf16* __restrict__ Bw,
                                                 const float* __restrict__ gate,
                                                 float* __restrict__ Y) {
    constexpr int KC = KTOT/32;
    constexpr int AST = 40;
    extern __shared__ char sm[];
    bf16* sAh = (bf16*)sm;
    bf16* sAl = (bf16*)(sm + 10240);
    bf16* sB  = (bf16*)(sm + 20480);
    float* sg = (float*)(sm + 51200);
    float (*sFP)[48] = (float(*)[48])(sm + 52096);
    int tid = threadIdx.x, lane = tid & 31, wid = tid >> 5;
    int wm = wid & 3, wn = wid >> 2;
    int half = blockIdx.y;
    size_t row0 = (size_t)blockIdx.x * 128;
    int b = blockIdx.x >> 7;           // 128 tiles per batch (CC*NN/128)
    int ch = (blockIdx.x >> 2) & 31;
    int tile = blockIdx.x & 3;
    const bf16* BwH = Bw + (size_t)half * 4*96*KTOT;

    if (G1) {
        for (int t = tid; t < KTOT; t += 256) sg[t] = 1.0f + gate[b*KTOT + t];
        __syncthreads();
    }

    float c1[2][6][4], c2[2][6][4];
#pragma unroll
    for (int f = 0; f < 2; f++)
#pragma unroll
        for (int i = 0; i < 6; i++)
#pragma unroll
            for (int j = 0; j < 4; j++) { c1[f][i][j] = 0.f; c2[f][i][j] = 0.f; }

    uint32_t aOff = (uint32_t)((wm*32 + (lane & 15))*AST + ((lane >> 4) << 3)) * 2;
    uint32_t aAddrH = smem_u32(sAh) + aOff;
    uint32_t aAddrL = smem_u32(sAl) + aOff;
    constexpr uint32_t FS = 16*AST*2;   // fragset-1 row offset (16 rows)
    uint32_t bRow = (uint32_t)(wn*48 + (lane & 7) + ((lane >> 4) << 3));
    uint32_t bOff = (bRow*AST + (((lane >> 3) & 1) << 3)) * 2;
    uint32_t sBbase = smem_u32(sB);

    int arow = tid >> 1, akg = (tid & 1) * 16;
    const float* xrow = X + (row0 + arow)*KTOT;
    bf16* aDstH = &sAh[arow*AST + akg];
    bf16* aDstL = &sAl[arow*AST + akg];

    float4 nx0, nx1, nx2, nx3;
    uint4 nB[6];
    {
        nx0 = *(const float4*)&xrow[akg];
        nx1 = *(const float4*)&xrow[akg + 4];
        nx2 = *(const float4*)&xrow[akg + 8];
        nx3 = *(const float4*)&xrow[akg + 12];
#pragma unroll
        for (int it = 0; it < 6; it++) {
            int i = tid + it*256;
            int mat = i / 384, rem = i % 384;
            int n = rem >> 2, kg = (rem & 3) * 8;
            nB[it] = *(const uint4*)&BwH[((size_t)mat*96 + n)*KTOT + kg];
        }
    }
    for (int kc = 0; kc < KC; kc++) {
        {
            int k0 = kc*32 + akg;
            float4 v0 = nx0, v1 = nx1, v2 = nx2, v3 = nx3;
            if (G1) {
                v0.x *= sg[k0];    v0.y *= sg[k0+1];  v0.z *= sg[k0+2];  v0.w *= sg[k0+3];
                v1.x *= sg[k0+4];  v1.y *= sg[k0+5];  v1.z *= sg[k0+6];  v1.w *= sg[k0+7];
                v2.x *= sg[k0+8];  v2.y *= sg[k0+9];  v2.z *= sg[k0+10]; v2.w *= sg[k0+11];
                v3.x *= sg[k0+12]; v3.y *= sg[k0+13]; v3.z *= sg[k0+14]; v3.w *= sg[k0+15];
            }
            cvt_hilo_store(v0, v1, aDstH, aDstL);
            cvt_hilo_store(v2, v3, aDstH + 8, aDstL + 8);
#pragma unroll
            for (int it = 0; it < 6; it++) {
                int i = tid + it*256;
                int mat = i / 384, rem = i % 384;
                int n = rem >> 2, kg = (rem & 3) * 8;
                *(uint4*)&sB[(mat*96 + n)*AST + kg] = nB[it];
            }
        }
        __syncthreads();
        if (kc + 1 < KC) {
            int kn = (kc + 1)*32;
            nx0 = *(const float4*)&xrow[kn + akg];
            nx1 = *(const float4*)&xrow[kn + akg + 4];
            nx2 = *(const float4*)&xrow[kn + akg + 8];
            nx3 = *(const float4*)&xrow[kn + akg + 12];
#pragma unroll
            for (int it = 0; it < 6; it++) {
                int i = tid + it*256;
                int mat = i / 384, rem = i % 384;
                int n = rem >> 2, kg = (rem & 3) * 8;
                nB[it] = *(const uint4*)&BwH[((size_t)mat*96 + n)*KTOT + kn + kg];
            }
        }
#pragma unroll
        for (int k16 = 0; k16 < 2; k16++) {
            uint32_t kof = (uint32_t)(k16 * 32);
            uint32_t ah0[4], al0[4], ah1[4], al1[4];
            LDM4(ah0, aAddrH + kof);
            LDM4(al0, aAddrL + kof);
            LDM4(ah1, aAddrH + FS + kof);
            LDM4(al1, aAddrL + FS + kof);
#pragma unroll
            for (int mat = 0; mat < 2; mat++) {
                uint32_t baseH = sBbase + (uint32_t)((mat*2 + 0)*96*AST)*2 + bOff + kof;
                uint32_t baseL = sBbase + (uint32_t)((mat*2 + 1)*96*AST)*2 + bOff + kof;
#pragma unroll
                for (int pr = 0; pr < 3; pr++) {
                    uint32_t po = (uint32_t)(pr*16*AST)*2;
                    uint32_t bh[4], bl[4];
                    LDM4(bh, baseH + po);
                    LDM4(bl, baseL + po);
                    float (*cf0)[4] = mat ? c2[0] : c1[0];
                    float (*cf1)[4] = mat ? c2[1] : c1[1];
                    MMA_BF16(cf0[2*pr],   ah0, bh[0], bh[1]);
                    MMA_BF16(cf0[2*pr+1], ah0, bh[2], bh[3]);
                    MMA_BF16(cf0[2*pr],   al0, bh[0], bh[1]);
                    MMA_BF16(cf0[2*pr+1], al0, bh[2], bh[3]);
                    MMA_BF16(cf0[2*pr],   ah0, bl[0], bl[1]);
                    MMA_BF16(cf0[2*pr+1], ah0, bl[2], bl[3]);
                    MMA_BF16(cf1[2*pr],   ah1, bh[0], bh[1]);
                    MMA_BF16(cf1[2*pr+1], ah1, bh[2], bh[3]);
                    MMA_BF16(cf1[2*pr],   al1, bh[0], bh[1]);
                    MMA_BF16(cf1[2*pr+1], al1, bh[2], bh[3]);
                    MMA_BF16(cf1[2*pr],   ah1, bl[0], bl[1]);
                    MMA_BF16(cf1[2*pr+1], ah1, bl[2], bl[3]);
                }
            }
        }
        __syncthreads();
    }

    // epilogue: o = (X@W1)*gelu(X@W2), store + column partial sums over 32 rows
    int g = lane >> 2, tg = lane & 3;
    int colb = half*96 + wn*48 + tg*2;
    float colsum[12];
#pragma unroll
    for (int i = 0; i < 12; i++) colsum[i] = 0.f;
#pragma unroll
    for (int f = 0; f < 2; f++) {
        size_t mrow = row0 + (size_t)wm*32 + f*16 + g;
#pragma unroll
        for (int nf = 0; nf < 6; nf++) {
            int col = colb + nf*8;
            float2 o0 = make_float2(c1[f][nf][0]*gelu_t(c2[f][nf][0]), c1[f][nf][1]*gelu_t(c2[f][nf][1]));
            float2 o1 = make_float2(c1[f][nf][2]*gelu_t(c2[f][nf][2]), c1[f][nf][3]*gelu_t(c2[f][nf][3]));
            *(float2*)&Y[mrow*KTOT + col] = o0;
            *(float2*)&Y[(mrow + 8)*KTOT + col] = o1;
            colsum[2*nf]   += o0.x + o1.x;
            colsum[2*nf+1] += o0.y + o1.y;
        }
    }
#pragma unroll
    for (int i = 0; i < 12; i++) {
        float v = colsum[i];
        v += __shfl_xor_sync(0xFFFFFFFF, v, 16);
        v += __shfl_xor_sync(0xFFFFFFFF, v, 8);
        v += __shfl_xor_sync(0xFFFFFFFF, v, 4);
        colsum[i] = v;
    }
    if (lane < 4) {
#pragma unroll
        for (int nf = 0; nf < 6; nf++) {
            sFP[wid][lane*2 + nf*8]     = colsum[2*nf];
            sFP[wid][lane*2 + nf*8 + 1] = colsum[2*nf+1];
        }
    }
    __syncthreads();
    if (tid < 96) {
        int wn2 = tid / 48, idx = tid % 48;
        float tot = sFP[wn2*4+0][idx] + sFP[wn2*4+1][idx] + sFP[wn2*4+2][idx] + sFP[wn2*4+3][idx];
        g_featP[((size_t)(b*CC + ch)*4 + tile)*KTOT + half*96 + wn2*48 + idx] = tot;
    }
}

// ---------------- attn gate (reads featP partials, 4 tiles) ----------------
template<int T>
__global__ void __launch_bounds__(T) k_gate(const float* __restrict__ Wq,
                                            const float* __restrict__ Wk) {
    __shared__ float ks[T][EE];
    int b = blockIdx.x, t = threadIdx.x;
    float q[EE], kk[EE];
#pragma unroll
    for (int e = 0; e < EE; e++) { q[e] = 0.f; kk[e] = 0.f; }
    for (int c = 0; c < CC; c++) {
        float f = 0.f;
#pragma unroll
        for (int p = 0; p < 4; p++) f += g_featP[((size_t)(b*CC + c)*4 + p)*T + t];
        f *= (1.0f/NN);
#pragma unroll
        for (int e = 0; e < EE; e++) {
            q[e]  = fmaf(f, Wq[c*EE + e], q[e]);
            kk[e] = fmaf(f, Wk[c*EE + e], kk[e]);
        }
    }
#pragma unroll
    for (int e = 0; e < EE; e++) ks[t][e] = kk[e];
    __syncthreads();
    float smax = -1e30f, stt = 0.f;
    for (int j = 0; j < T; j++) {
        float d = 0.f;
#pragma unroll
        for (int e = 0; e < EE; e++) d = fmaf(q[e], ks[j][e], d);
        d *= 0.125f;
        if (j == t) stt = d;
        smax = fmaxf(smax, d);
    }
    float ssum = 0.f;
    for (int j = 0; j < T; j++) {
        float d = 0.f;
#pragma unroll
        for (int e = 0; e < EE; e++) d = fmaf(q[e], ks[j][e], d);
        ssum += expf(d*0.125f - smax);
    }
    float p = expf(stt - smax) / ssum;
    g_gate[b*T + t] = gelu_t(p);
}

// ---------------- driver ----------------
extern "C" void kernel_launch(void* const* d_in, const int* in_sizes, int n_in,
                              void* d_out, int out_size) {
    const float* x   = (const float*)d_in[0];
    const float* Gc  = (const float*)d_in[3];
    const float* Lc  = (const float*)d_in[4];
    const float* Gt  = (const float*)d_in[5];
    const float* Lt  = (const float*)d_in[6];
    const float* f1r = (const float*)d_in[7];
    const float* f1i = (const float*)d_in[8];
    const float* f2r = (const float*)d_in[9];
    const float* f2i = (const float*)d_in[10];
    const float* Wfc = (const float*)d_in[11];
    const float* bfc = (const float*)d_in[12];
    const float* mi1 = (const float*)d_in[13];
    const float* mi2 = (const float*)d_in[14];
    const float* mo1 = (const float*)d_in[15];
    const float* mo2 = (const float*)d_in[16];
    const float* aiq = (const float*)d_in[17];
    const float* aik = (const float*)d_in[18];
    const float* aoq = (const float*)d_in[19];
    const float* aok = (const float*)d_in[20];
    float* out = (float*)d_out;

    float *bufA, *bufB, *bufC, *bufD, *bufF, *gate;
    bf16 *Bin, *Bout, *D1B, *C2B;
    cudaGetSymbolAddress((void**)&bufA, g_bufA);
    cudaGetSymbolAddress((void**)&bufB, g_bufB);
    cudaGetSymbolAddress((void**)&bufC, g_bufC);
    cudaGetSymbolAddress((void**)&bufD, g_bufD);
    cudaGetSymbolAddress((void**)&bufF, g_bufF);
    cudaGetSymbolAddress((void**)&gate, g_gate);
    cudaGetSymbolAddress((void**)&Bin,  g_Bin);
    cudaGetSymbolAddress((void**)&Bout, g_Bout);
    cudaGetSymbolAddress((void**)&D1B,  g_D1B);
    cudaGetSymbolAddress((void**)&C2B,  g_C2B);

    constexpr int SMEM_G = 53632;
    cudaFuncSetAttribute(k_gmlpMMA<T1,false>, cudaFuncAttributeMaxDynamicSharedMemorySize, SMEM_G);
    cudaFuncSetAttribute(k_gmlpMMA<T1,true >, cudaFuncAttributeMaxDynamicSharedMemorySize, SMEM_G);
    cudaFuncSetAttribute(k_gmlpMMA<T2,false>, cudaFuncAttributeMaxDynamicSharedMemorySize, SMEM_G);
    cudaFuncSetAttribute(k_gmlpMMA<T2,true >, cudaFuncAttributeMaxDynamicSharedMemorySize, SMEM_G);

    // precompute operator matrices + weight splits
    k_tables<<<(L1*T1 + L2*T2 + 255)/256, 256>>>();
    k_buildM<<<dim3(T1, CC), T1>>>(Lc, Lt);
    k_buildK1<<<(CC*T1 + 255)/256, 256>>>(f1r, f1i);
    k_buildD1<<<dim3(T1, CC), T2>>>(Wfc);
    k_buildK2<<<(CC*T2 + 255)/256, 256>>>(f2r, f2i);
    k_expand2<<<(int)(((size_t)CC*T2*T2 + 255)/256), 256>>>();
    k_splitW<T1,2><<<(2*2*4*96*T1 + 255)/256, 256>>>(mi1, mi2, Bin);
    k_splitW<T2,1><<<(2*1*4*96*T2 + 255)/256, 256>>>(mo1, mo2, Bout);
    k_splitMM<<<(int)(((size_t)CC*2*192*384 + 255)/256), 256>>>();
    k_splitD1<<<(CC*2*96*T1 + 255)/256, 256>>>();
    k_splitC2<<<(CC*2*96*T2 + 255)/256, 256>>>();

    // freq_attn_in: u = Gc^T x, v = Gt^T x ; xc = x + u@Mc[c] + v@Mt[c]
    k_chmix<<<dim3(NN*T1/256, BB), 256>>>(x, Gc, Gt);
    k_mm2MMA<<<dim3(NN/64, CC, BB), 256>>>(bufA, bufB, x, bufC);

    const int NT = BB*CC*NN/128;              // 2048 M-tiles of 128 rows
    const size_t L1OFF = (size_t)2*4*96*T1;
    const size_t L2OFF = (size_t)1*4*96*T2;

    // input-side layers (tensor core, n-mean fused)
    k_gmlpMMA<T1,false><<<dim3(NT, 2), 256, SMEM_G>>>(bufC, Bin, nullptr, bufA);
    k_gate<T1><<<BB, T1>>>(aiq, aik);
    k_gmlpMMA<T1,true ><<<dim3(NT, 2), 256, SMEM_G>>>(bufA, Bin + L1OFF, gate, bufC);
    k_gate<T1><<<BB, T1>>>(aiq + CC*EE, aik + CC*EE);

    // h_y = (x + xc*(1+g)) @ D1[c] + bfc   (fconv1 + fc_idp fused, tensor)
    k_cgemmMMA<T1, true><<<dim3(NN/64, CC, BB), 256>>>(x, bufC, D1B, bfc, gate, bufD);

    // output-side layers (tensor core, n-mean fused)
    k_gmlpMMA<T2,false><<<dim3(NT, 1), 256, SMEM_G>>>(bufD, Bout, nullptr, bufA);
    k_gate<T2><<<BB, T2>>>(aoq, aok);
    k_gmlpMMA<T2,true ><<<dim3(NT, 1), 256, SMEM_G>>>(bufA, Bout + L2OFF, gate, bufF);
    k_gate<T2><<<BB, T2>>>(aoq + CC*EE, aok + CC*EE);

    // out = (h_y + y_c*(1+g)) @ C2[c]   (tensor)
    k_cgemmMMA<T2, false><<<dim3(NN/64, CC, BB), 256>>>(bufD, bufF, C2B, nullptr, gate, out);
}